// round 15
// baseline (speedup 1.0000x reference)
#include <cuda_runtime.h>

#define BATCH 2
#define NPTS  16384
#define NKP   4096
#define TOTKP (BATCH*NKP)
#define CCAP  384
#define R2A_CONST ((float)(0.8*0.8))
#define R2B_CONST ((float)(1.6*1.6))
#define NTHR  1024
#define PPT   16
#define NCELLS 512

__device__ float g_kp_xyz[TOTKP*3];
__device__ int   g_kp_sorted[TOTKP];
__device__ float4 g_sorted4[BATCH*NPTS];
__device__ int   g_cell_end[BATCH*NCELLS];
__device__ float g_grid[BATCH*8];
__device__ float g_cand_d[TOTKP*CCAP];
__device__ int   g_cand_i[TOTKP*CCAP];
__device__ int   g_cand_cnt[TOTKP];
__device__ int   g_nbr[TOTKP*32];
__device__ int   g_cnt_a[TOTKP];
__device__ int   g_cnt_b[TOTKP];
__device__ float g_pooled[TOTKP*512];

__device__ __forceinline__ float dist2_ref(float dx, float dy, float dz) {
    return __fadd_rn(__fadd_rn(__fmul_rn(dx,dx), __fmul_rn(dy,dy)), __fmul_rn(dz,dz));
}
__device__ __forceinline__ unsigned fenc(float f) {   // monotone for f >= 0
    return __float_as_uint(f) | 0x80000000u;
}
__device__ __forceinline__ unsigned fenc_s(float f) { // full monotone encode
    unsigned u = __float_as_uint(f);
    return (u & 0x80000000u) ? ~u : (u | 0x80000000u);
}
__device__ __forceinline__ float fdec_s(unsigned u) {
    return __uint_as_float((u & 0x80000000u) ? (u & 0x7fffffffu) : ~u);
}
__device__ __forceinline__ int mort4(int v) {
    v = (v | (v << 2)) & 0x33;
    v = (v | (v << 1)) & 0x55;
    return v;
}
// packed f32x2 FMA helpers (bit-identical IEEE fp32 per lane)
__device__ __forceinline__ void ffma2(unsigned long long& acc, unsigned long long h2,
                                      unsigned long long w2) {
    asm("fma.rn.f32x2 %0, %1, %2, %0;" : "+l"(acc) : "l"(h2), "l"(w2));
}
__device__ __forceinline__ unsigned long long dup2(float w) {
    unsigned long long r;
    asm("mov.b64 %0, {%1, %1};" : "=l"(r) : "r"(__float_as_uint(w)));
    return r;
}
__device__ __forceinline__ float pairmax(unsigned long long a) {
    unsigned lo, hi;
    asm("mov.b64 {%0, %1}, %2;" : "=r"(lo), "=r"(hi) : "l"(a));
    return fmaxf(__uint_as_float(lo), __uint_as_float(hi));
}

// ===== K1: FPS — 1024thr/PPT16, warp-level bbox skip, branchless compare =====
extern __shared__ unsigned char dsm[];

__global__ __launch_bounds__(NTHR,1) void fps_kernel(const float* __restrict__ clouds) {
    int b = blockIdx.x;
    float2* sxyT = (float2*)dsm;                    // packed (x,y) per point
    float*  szT  = (float*)(sxyT + NPTS);
    unsigned short* spermT = (unsigned short*)(szT + NPTS);
    unsigned int*   hist   = (unsigned int*)(spermT + NPTS);
    uint2* wk0 = (uint2*)(hist + NCELLS);           // key buffers (32 warps), 2 parities
    uint2* wk1 = wk0 + 32;
    unsigned int* s_bb = (unsigned int*)(wk1 + 32); // [0..5] bbox encoded
    int* s_p0 = (int*)(s_bb + 6);

    const float* cb = clouds + (size_t)b*4*NPTS;
    int t = threadIdx.x, lane = t & 31, w = t >> 5;

    if (t < 3)      s_bb[t] = 0xFFFFFFFFu;
    else if (t < 6) s_bb[t] = 0u;
    for (int c = t; c < NCELLS; c += NTHR) hist[c] = 0;
    __syncthreads();
    {
        float mnx=1e30f,mny=1e30f,mnz=1e30f,mxx=-1e30f,mxy=-1e30f,mxz=-1e30f;
        for (int j = 0; j < PPT; j++) {
            int i = t + j*NTHR;
            float x = cb[i], y = cb[NPTS+i], z = cb[2*NPTS+i];
            mnx = fminf(mnx,x); mny = fminf(mny,y); mnz = fminf(mnz,z);
            mxx = fmaxf(mxx,x); mxy = fmaxf(mxy,y); mxz = fmaxf(mxz,z);
        }
        #pragma unroll
        for (int off = 16; off > 0; off >>= 1) {
            mnx = fminf(mnx, __shfl_down_sync(0xffffffffu, mnx, off));
            mny = fminf(mny, __shfl_down_sync(0xffffffffu, mny, off));
            mnz = fminf(mnz, __shfl_down_sync(0xffffffffu, mnz, off));
            mxx = fmaxf(mxx, __shfl_down_sync(0xffffffffu, mxx, off));
            mxy = fmaxf(mxy, __shfl_down_sync(0xffffffffu, mxy, off));
            mxz = fmaxf(mxz, __shfl_down_sync(0xffffffffu, mxz, off));
        }
        if (lane == 0) {
            atomicMin(&s_bb[0], fenc_s(mnx));
            atomicMin(&s_bb[1], fenc_s(mny));
            atomicMin(&s_bb[2], fenc_s(mnz));
            atomicMax(&s_bb[3], fenc_s(mxx));
            atomicMax(&s_bb[4], fenc_s(mxy));
            atomicMax(&s_bb[5], fenc_s(mxz));
        }
    }
    __syncthreads();
    float gminx = fdec_s(s_bb[0]), gminy = fdec_s(s_bb[1]), gminz = fdec_s(s_bb[2]);
    float grx = 16.0f / fmaxf(fdec_s(s_bb[3]) - gminx, 1e-9f);
    float gry = 16.0f / fmaxf(fdec_s(s_bb[4]) - gminy, 1e-9f);
    float grz = 2.0f  / fmaxf(fdec_s(s_bb[5]) - gminz, 1e-9f);

    for (int j = 0; j < PPT; j++) {
        int i = t + j*NTHR;
        int cx = min(15, (int)((cb[i]        - gminx) * grx));
        int cy = min(15, (int)((cb[NPTS+i]   - gminy) * gry));
        int cz = min(1,  (int)((cb[2*NPTS+i] - gminz) * grz));
        int cell = (((mort4(cy) << 1) | mort4(cx)) << 1) | cz;
        atomicAdd(&hist[cell], 1u);
    }
    __syncthreads();
    for (int off = 1; off < NCELLS; off <<= 1) {
        unsigned v = 0;
        if (t < NCELLS && t >= off) v = hist[t-off];
        __syncthreads();
        if (t < NCELLS) hist[t] += v;
        __syncthreads();
    }
    {
        unsigned v = (t == 0) ? 0u : ((t < NCELLS) ? hist[t-1] : 0u);
        __syncthreads();
        if (t < NCELLS) hist[t] = v;
        __syncthreads();
    }
    for (int j = 0; j < PPT; j++) {
        int i = t + j*NTHR;
        float x = cb[i], y = cb[NPTS+i], z = cb[2*NPTS+i];
        int cx = min(15, (int)((x - gminx) * grx));
        int cy = min(15, (int)((y - gminy) * gry));
        int cz = min(1,  (int)((z - gminz) * grz));
        int cell = (((mort4(cy) << 1) | mort4(cx)) << 1) | cz;
        int p = (int)atomicAdd(&hist[cell], 1u);
        int phys = (p & 15)*NTHR + (p >> 4);
        sxyT[phys] = make_float2(x, y);
        szT[phys] = z;
        spermT[phys] = (unsigned short)i;
        if (i == 0) *s_p0 = p;
    }
    __syncthreads();

    float dmin[PPT];
    float bxmin=1e30f, bymin=1e30f, bzmin=1e30f, bxmax=-1e30f, bymax=-1e30f, bzmax=-1e30f;
    #pragma unroll
    for (int j = 0; j < PPT; j++) {
        dmin[j] = 1e10f;
        float2 xy = sxyT[j*NTHR + t];
        float z = szT[j*NTHR + t];
        bxmin = fminf(bxmin,xy.x); bymin = fminf(bymin,xy.y); bzmin = fminf(bzmin,z);
        bxmax = fmaxf(bxmax,xy.x); bymax = fmaxf(bymax,xy.y); bzmax = fmaxf(bzmax,z);
    }
    // warp-union bbox (all lanes hold result via xor-shuffles)
    float wxmin=bxmin, wymin=bymin, wzmin=bzmin, wxmax=bxmax, wymax=bymax, wzmax=bzmax;
    #pragma unroll
    for (int off = 16; off > 0; off >>= 1) {
        wxmin = fminf(wxmin, __shfl_xor_sync(0xffffffffu, wxmin, off));
        wymin = fminf(wymin, __shfl_xor_sync(0xffffffffu, wymin, off));
        wzmin = fminf(wzmin, __shfl_xor_sync(0xffffffffu, wzmin, off));
        wxmax = fmaxf(wxmax, __shfl_xor_sync(0xffffffffu, wxmax, off));
        wymax = fmaxf(wymax, __shfl_xor_sync(0xffffffffu, wymax, off));
        wzmax = fmaxf(wzmax, __shfl_xor_sync(0xffffffffu, wzmax, off));
    }

    float bestv = 1e10f; int bestorig = 0x3fff; int bestsorted = t*PPT;
    float warp_bestv = 1e10f;            // = max lane bestv (decoded from wkh)
    unsigned wkh = 0u, wkl = 0u;
    unsigned champ_mask = 0xffffffffu;   // force reduce on first update
    int last = *s_p0;

    for (int it = 0; it < NKP; ++it) {
        if (t == 0) g_kp_sorted[b*NKP + it] = last;
        if (it == NKP-1) break;

        int lphys = (last & 15)*NTHR + (last >> 4);
        float2 lxy = sxyT[lphys];
        float lz = szT[lphys];
        float lx = lxy.x, ly = lxy.y;

        // ---- warp-level skip: uniform across lanes ----
        float wdx = fmaxf(fmaxf(wxmin - lx, lx - wxmax), 0.f);
        float wdy = fmaxf(fmaxf(wymin - ly, ly - wymax), 0.f);
        float wdz = fmaxf(fmaxf(wzmin - lz, lz - wzmax), 0.f);
        float wd2 = fmaf(wdx, wdx, fmaf(wdy, wdy, wdz*wdz));
        if ((wd2 * 0.99999f) < warp_bestv) {
            float dx = fmaxf(fmaxf(bxmin - lx, lx - bxmax), 0.f);
            float dy = fmaxf(fmaxf(bymin - ly, ly - bymax), 0.f);
            float dz = fmaxf(fmaxf(bzmin - lz, lz - bzmax), 0.f);
            float d2b = fmaf(dx, dx, fmaf(dy, dy, dz*dz));
            bool need = (d2b * 0.99999f) < bestv;

            if (need) {
                float bv = -1.f; int bo = 0x3fff, bs = t*PPT;
                #pragma unroll
                for (int j = 0; j < PPT; j++) {
                    int phys = j*NTHR + t;
                    float2 xy = sxyT[phys];
                    float d  = dist2_ref(xy.x-lx, xy.y-ly, szT[phys]-lz);
                    float nd = fminf(dmin[j], d);
                    dmin[j] = nd;
                    int o = (int)spermT[phys];
                    if (nd > bv || (nd == bv && o < bo)) { bv = nd; bo = o; bs = t*PPT + j; }
                }
                bestv = bv; bestorig = bo; bestsorted = bs;
            }
            unsigned m = __ballot_sync(0xffffffffu, need);
            if (m & champ_mask) {
                unsigned fv = fenc(bestv);
                wkh = __reduce_max_sync(0xffffffffu, fv);
                unsigned lo = (fv == wkh) ? (((unsigned)(0x3fff - bestorig) << 14) | (unsigned)bestsorted) : 0u;
                wkl = __reduce_max_sync(0xffffffffu, lo);
                champ_mask = __ballot_sync(0xffffffffu, fv == wkh && lo == wkl);
                warp_bestv = __uint_as_float(wkh & 0x7fffffffu);
            }
        }
        uint2* wkb = (it & 1) ? wk1 : wk0;
        if (lane == 0) wkb[w] = make_uint2(wkh, wkl);
        __syncthreads();
        uint2 k = wkb[lane];
        unsigned mh = __reduce_max_sync(0xffffffffu, k.x);
        unsigned ml = __reduce_max_sync(0xffffffffu, (k.x == mh) ? k.y : 0u);
        last = (int)(ml & 0x3fffu);
        // single barrier per iter: double-buffered key table makes it race-free
    }
    __syncthreads();

    for (int k = t; k < NKP; k += NTHR) {
        int p = g_kp_sorted[b*NKP + k];
        int phys = (p & 15)*NTHR + (p >> 4);
        float2 xy = sxyT[phys];
        g_kp_xyz[(b*NKP+k)*3+0] = xy.x;
        g_kp_xyz[(b*NKP+k)*3+1] = xy.y;
        g_kp_xyz[(b*NKP+k)*3+2] = szT[phys];
    }
    for (int p = t; p < NPTS; p += NTHR) {
        int phys = (p & 15)*NTHR + (p >> 4);
        float2 xy = sxyT[phys];
        g_sorted4[b*NPTS + p] = make_float4(xy.x, xy.y, szT[phys],
                                            __int_as_float((int)spermT[phys]));
    }
    for (int c = t; c < NCELLS; c += NTHR) g_cell_end[b*NCELLS + c] = (int)hist[c];
    if (t == 0) {
        g_grid[b*8+0] = gminx; g_grid[b*8+1] = gminy; g_grid[b*8+2] = gminz;
        g_grid[b*8+3] = grx;   g_grid[b*8+4] = gry;   g_grid[b*8+5] = grz;
    }
}

// ============ K2: cell-pruned ball query (one warp per keypoint) ============
__global__ __launch_bounds__(256) void ballq_kernel() {
    int kp = blockIdx.x * 8 + (threadIdx.x >> 5);
    int b = kp >> 12, lane = threadIdx.x & 31;
    float kx = g_kp_xyz[kp*3+0], ky = g_kp_xyz[kp*3+1], kz = g_kp_xyz[kp*3+2];
    float gminx = g_grid[b*8+0], gminy = g_grid[b*8+1], gminz = g_grid[b*8+2];
    float grx = g_grid[b*8+3], gry = g_grid[b*8+4], grz = g_grid[b*8+5];
    const float4* sp4 = g_sorted4 + b*NPTS;
    const int* cend = g_cell_end + b*NCELLS;

    const float R = 1.6005f;
    int cx0 = max(0, min(15, (int)floorf((kx - R - gminx) * grx)));
    int cx1 = max(0, min(15, (int)floorf((kx + R - gminx) * grx)));
    int cy0 = max(0, min(15, (int)floorf((ky - R - gminy) * gry)));
    int cy1 = max(0, min(15, (int)floorf((ky + R - gminy) * gry)));
    int cz0 = max(0, min(1,  (int)floorf((kz - R - gminz) * grz)));
    int cz1 = max(0, min(1,  (int)floorf((kz + R - gminz) * grz)));

    int cnt = 0;
    unsigned lmask = (1u << lane) - 1u;
    for (int cy = cy0; cy <= cy1; cy++) {
        for (int cx = cx0; cx <= cx1; cx++) {
            int base = ((mort4(cy) << 1) | mort4(cx)) << 1;
            int c0 = base | cz0, c1 = base | cz1;
            int pstart = (c0 == 0) ? 0 : cend[c0-1];
            int pend = cend[c1];
            for (int p0 = pstart; p0 < pend; p0 += 32) {   // uniform trip count
                int p = p0 + lane;
                bool in = p < pend;
                float4 P = in ? sp4[p] : make_float4(1e30f, 1e30f, 1e30f, 0.f);
                float d2 = dist2_ref(kx - P.x, ky - P.y, kz - P.z);
                bool hit = in && (d2 < R2B_CONST);
                unsigned m = __ballot_sync(0xffffffffu, hit);
                if (hit) {
                    int pos = cnt + __popc(m & lmask);
                    if (pos < CCAP) {
                        g_cand_d[kp*CCAP + pos] = d2;
                        g_cand_i[kp*CCAP + pos] = __float_as_int(P.w);
                    }
                }
                cnt += __popc(m);
            }
        }
    }
    if (lane == 0) g_cand_cnt[kp] = (cnt < CCAP) ? cnt : CCAP;
}

// ============ K3: rank candidates (one warp per keypoint) ============
__global__ __launch_bounds__(256) void select_kernel() {
    __shared__ float sd[8*CCAP];
    __shared__ int   si[8*CCAP];
    int w = threadIdx.x >> 5, lane = threadIdx.x & 31;
    int kp = blockIdx.x * 8 + w;
    float* swd = sd + w*CCAP; int* swi = si + w*CCAP;
    int n = g_cand_cnt[kp];
    for (int c = lane; c < n; c += 32) {
        swd[c] = g_cand_d[kp*CCAP + c];
        swi[c] = g_cand_i[kp*CCAP + c];
    }
    __syncwarp();
    int na = 0;
    for (int c = lane; c < n; c += 32) {
        float dc = swd[c];
        int oc = swi[c];
        int rank = 0;
        for (int c2 = 0; c2 < n; c2++) {
            float dv = swd[c2];
            rank += (dv < dc) || (dv == dc && swi[c2] < oc);
        }
        if (rank < 32) g_nbr[kp*32 + rank] = oc;
        if (rank < 16 && dc < R2A_CONST) na++;
    }
    #pragma unroll
    for (int off = 16; off > 0; off >>= 1) na += __shfl_down_sync(0xffffffffu, na, off);
    if (lane == 0) {
        g_cnt_a[kp] = na;
        g_cnt_b[kp] = (n < 32) ? n : 32;
    }
}

// ============ K4: PointNet MLP + max pool — register-tiled, relu-clamped ============
__global__ __launch_bounds__(256) void mlp_kernel(const float* __restrict__ clouds,
                                                  const float* __restrict__ w1a,
                                                  const float* __restrict__ w2a,
                                                  const float* __restrict__ w1b,
                                                  const float* __restrict__ w2b) {
    int kp = blockIdx.x;
    int b  = kp >> 12;
    __shared__ float sg[32][5];
    __shared__ float h1bt[128*32];
    __shared__ float h1at[128*16];
    __shared__ float partb[4][256];
    __shared__ float parta[2][256];
    __shared__ int   s_ca, s_cb;
    int t = threadIdx.x;
    if (t == 0) { s_ca = g_cnt_a[kp]; s_cb = g_cnt_b[kp]; }
    __syncthreads();
    int ca = s_ca, cb2 = s_cb;

    if (t < 32 && t < cb2) {
        int pi = g_nbr[kp*32 + t];
        const float* cbase = clouds + (size_t)b*4*NPTS;
        sg[t][0] = cbase[pi]        - g_kp_xyz[kp*3+0];
        sg[t][1] = cbase[NPTS+pi]   - g_kp_xyz[kp*3+1];
        sg[t][2] = cbase[2*NPTS+pi] - g_kp_xyz[kp*3+2];
        sg[t][3] = cbase[3*NPTS+pi];
    }
    __syncthreads();

    for (int e = t; e < 128*32; e += 256) {
        int j = e & 31, i = e >> 5;
        float v = 0.f;
        if (j < cb2) {
            float a = __fmul_rn(sg[j][0], w1b[i]);
            a = fmaf(sg[j][1], w1b[128+i], a);
            a = fmaf(sg[j][2], w1b[256+i], a);
            a = fmaf(sg[j][3], w1b[384+i], a);
            v = fmaxf(a, 0.f);
        }
        h1bt[i*32 + j] = v;
    }
    for (int e = t; e < 128*16; e += 256) {
        int j = e & 15, i = e >> 4;
        float v = 0.f;
        if (j < ca) {
            float a = __fmul_rn(sg[j][0], w1a[i]);
            a = fmaf(sg[j][1], w1a[128+i], a);
            a = fmaf(sg[j][2], w1a[256+i], a);
            a = fmaf(sg[j][3], w1a[384+i], a);
            v = fmaxf(a, 0.f);
        }
        h1at[i*16 + j] = v;
    }
    __syncthreads();

    // ---- scale b: thread = (jg = t>>6 in 0..3, cq = t&63 -> channels cq*4..+3) ----
    {
        int jg = t >> 6, cq = t & 63;
        unsigned long long acc[16];
        #pragma unroll
        for (int q = 0; q < 16; q++) acc[q] = 0ull;
        const float4* w2b4 = reinterpret_cast<const float4*>(w2b);
        for (int i = 0; i < 128; i++) {
            const ulonglong2* hp = reinterpret_cast<const ulonglong2*>(h1bt + i*32 + jg*8);
            ulonglong2 ha = hp[0], hb = hp[1];          // 8 j values = 4 pairs
            float4 wq = __ldg(&w2b4[i*64 + cq]);
            unsigned long long w0 = dup2(wq.x), w1 = dup2(wq.y),
                               w2d = dup2(wq.z), w3 = dup2(wq.w);
            ffma2(acc[0],  ha.x, w0); ffma2(acc[1],  ha.y, w0);
            ffma2(acc[2],  hb.x, w0); ffma2(acc[3],  hb.y, w0);
            ffma2(acc[4],  ha.x, w1); ffma2(acc[5],  ha.y, w1);
            ffma2(acc[6],  hb.x, w1); ffma2(acc[7],  hb.y, w1);
            ffma2(acc[8],  ha.x, w2d); ffma2(acc[9],  ha.y, w2d);
            ffma2(acc[10], hb.x, w2d); ffma2(acc[11], hb.y, w2d);
            ffma2(acc[12], ha.x, w3); ffma2(acc[13], ha.y, w3);
            ffma2(acc[14], hb.x, w3); ffma2(acc[15], hb.y, w3);
        }
        #pragma unroll
        for (int c = 0; c < 4; c++) {
            float v = fmaxf(fmaxf(pairmax(acc[c*4+0]), pairmax(acc[c*4+1])),
                            fmaxf(pairmax(acc[c*4+2]), pairmax(acc[c*4+3])));
            partb[jg][cq*4 + c] = v;
        }
    }

    // ---- scale a: thread = (jg2 = t>>7 in 0..1, cd = t&127 -> channels cd*2..+1) ----
    {
        int jg2 = t >> 7, cd = t & 127;
        unsigned long long acc[8];
        #pragma unroll
        for (int q = 0; q < 8; q++) acc[q] = 0ull;
        const float2* w2a2 = reinterpret_cast<const float2*>(w2a);
        for (int i = 0; i < 128; i++) {
            const ulonglong2* hp = reinterpret_cast<const ulonglong2*>(h1at + i*16 + jg2*8);
            ulonglong2 ha = hp[0], hb = hp[1];
            float2 wq = __ldg(&w2a2[i*128 + cd]);
            unsigned long long w0 = dup2(wq.x), w1 = dup2(wq.y);
            ffma2(acc[0], ha.x, w0); ffma2(acc[1], ha.y, w0);
            ffma2(acc[2], hb.x, w0); ffma2(acc[3], hb.y, w0);
            ffma2(acc[4], ha.x, w1); ffma2(acc[5], ha.y, w1);
            ffma2(acc[6], hb.x, w1); ffma2(acc[7], hb.y, w1);
        }
        #pragma unroll
        for (int c = 0; c < 2; c++) {
            float v = fmaxf(fmaxf(pairmax(acc[c*4+0]), pairmax(acc[c*4+1])),
                            fmaxf(pairmax(acc[c*4+2]), pairmax(acc[c*4+3])));
            parta[jg2][cd*2 + c] = v;
        }
    }
    __syncthreads();

    if (t < 64) {   // b channels: 4 per thread; relu clamp matches reference
        #pragma unroll
        for (int c = 0; c < 4; c++) {
            int ch = t*4 + c;
            float v = fmaxf(fmaxf(partb[0][ch], partb[1][ch]),
                            fmaxf(partb[2][ch], partb[3][ch]));
            g_pooled[kp*512 + 256 + ch] = fmaxf(v, 0.f);
        }
    } else if (t >= 128) {   // a channels: 2 per thread
        int tt = t - 128;
        #pragma unroll
        for (int c = 0; c < 2; c++) {
            int ch = tt*2 + c;
            float v = fmaxf(parta[0][ch], parta[1][ch]);
            g_pooled[kp*512 + ch] = fmaxf(v, 0.f);
        }
    }
}

// ============ K5: fusion + output (16 kp per block) ============
__global__ __launch_bounds__(128) void fuse_kernel(const float* __restrict__ wf,
                                                   float* __restrict__ out) {
    int kp0 = blockIdx.x * 16;
    __shared__ float sp[512*16];
    int t = threadIdx.x;
    for (int e = t; e < 512*16; e += 128) {
        int c = e & 511, q = e >> 9;
        sp[c*16 + q] = g_pooled[(size_t)(kp0 + q)*512 + c];
    }
    __syncthreads();
    unsigned long long acc[8];
    #pragma unroll
    for (int q = 0; q < 8; q++) acc[q] = 0ull;
    for (int c = 0; c < 512; c++) {
        unsigned long long wd = dup2(__ldg(&wf[c*128 + t]));
        const ulonglong2* pr = reinterpret_cast<const ulonglong2*>(sp + c*16);
        #pragma unroll
        for (int q4 = 0; q4 < 4; q4++) {
            ulonglong2 p2 = pr[q4];
            ffma2(acc[q4*2+0], p2.x, wd);
            ffma2(acc[q4*2+1], p2.y, wd);
        }
    }
    #pragma unroll
    for (int q = 0; q < 8; q++) {
        unsigned lo, hi;
        asm("mov.b64 {%0, %1}, %2;" : "=r"(lo), "=r"(hi) : "l"(acc[q]));
        out[(size_t)(kp0+q*2+0)*131 + 3 + t] = fmaxf(__uint_as_float(lo), 0.f);
        out[(size_t)(kp0+q*2+1)*131 + 3 + t] = fmaxf(__uint_as_float(hi), 0.f);
    }
    if (t < 48) {
        int q = t / 3, comp = t % 3;
        out[(size_t)(kp0+q)*131 + comp] = g_kp_xyz[(kp0+q)*3 + comp];
    }
}

extern "C" void kernel_launch(void* const* d_in, const int* in_sizes, int n_in,
                              void* d_out, int out_size) {
    const float* clouds = (const float*)d_in[0];
    const float* w1a    = (const float*)d_in[1];
    const float* w2a    = (const float*)d_in[2];
    const float* w1b    = (const float*)d_in[3];
    const float* w2b    = (const float*)d_in[4];
    const float* wf     = (const float*)d_in[5];
    float* out = (float*)d_out;

    // xy(float2) + z + perm + hist + 2x32 uint2 keys + bbox(6) + p0
    int fps_smem = NPTS*8 + NPTS*4 + NPTS*2 + NCELLS*4 + 2*32*8 + 6*4 + 16;
    cudaFuncSetAttribute(fps_kernel, cudaFuncAttributeMaxDynamicSharedMemorySize, fps_smem);
    fps_kernel<<<BATCH, NTHR, fps_smem>>>(clouds);

    ballq_kernel<<<TOTKP/8, 256>>>();
    select_kernel<<<TOTKP/8, 256>>>();
    mlp_kernel<<<TOTKP, 256>>>(clouds, w1a, w2a, w1b, w2b);
    fuse_kernel<<<TOTKP/16, 128>>>(wf, out);
}

// round 16
// speedup vs baseline: 1.0706x; 1.0706x over previous
#include <cuda_runtime.h>

#define BATCH 2
#define NPTS  16384
#define NKP   4096
#define TOTKP (BATCH*NKP)
#define CCAP  384
#define R2A_CONST ((float)(0.8*0.8))
#define R2B_CONST ((float)(1.6*1.6))
#define NTHR  1024
#define PPT   16
#define NCELLS 512

__device__ float g_kp_xyz[TOTKP*3];
__device__ int   g_kp_sorted[TOTKP];
__device__ float4 g_sorted4[BATCH*NPTS];
__device__ int   g_cell_end[BATCH*NCELLS];
__device__ float g_grid[BATCH*8];
__device__ int   g_nbr[TOTKP*32];
__device__ int   g_cnt_a[TOTKP];
__device__ int   g_cnt_b[TOTKP];
__device__ float g_pooled[TOTKP*512];

__device__ __forceinline__ float dist2_ref(float dx, float dy, float dz) {
    return __fadd_rn(__fadd_rn(__fmul_rn(dx,dx), __fmul_rn(dy,dy)), __fmul_rn(dz,dz));
}
__device__ __forceinline__ unsigned fenc(float f) {   // monotone for f >= 0
    return __float_as_uint(f) | 0x80000000u;
}
__device__ __forceinline__ unsigned fenc_s(float f) { // full monotone encode
    unsigned u = __float_as_uint(f);
    return (u & 0x80000000u) ? ~u : (u | 0x80000000u);
}
__device__ __forceinline__ float fdec_s(unsigned u) {
    return __uint_as_float((u & 0x80000000u) ? (u & 0x7fffffffu) : ~u);
}
__device__ __forceinline__ int mort4(int v) {
    v = (v | (v << 2)) & 0x33;
    v = (v | (v << 1)) & 0x55;
    return v;
}
// packed f32x2 FMA helpers (bit-identical IEEE fp32 per lane)
__device__ __forceinline__ void ffma2(unsigned long long& acc, unsigned long long h2,
                                      unsigned long long w2) {
    asm("fma.rn.f32x2 %0, %1, %2, %0;" : "+l"(acc) : "l"(h2), "l"(w2));
}
__device__ __forceinline__ unsigned long long dup2(float w) {
    unsigned long long r;
    asm("mov.b64 %0, {%1, %1};" : "=l"(r) : "r"(__float_as_uint(w)));
    return r;
}
__device__ __forceinline__ float pairmax(unsigned long long a) {
    unsigned lo, hi;
    asm("mov.b64 {%0, %1}, %2;" : "=r"(lo), "=r"(hi) : "l"(a));
    return fmaxf(__uint_as_float(lo), __uint_as_float(hi));
}

// ============ K1: FPS — 1024thr/PPT16, branchless compare, champ-mask ============
// (byte-identical to the measured 3406us / rel_err 0.0 version)
extern __shared__ unsigned char dsm[];

__global__ __launch_bounds__(NTHR,1) void fps_kernel(const float* __restrict__ clouds) {
    int b = blockIdx.x;
    float* sxT = (float*)dsm;
    float* syT = sxT + NPTS;
    float* szT = syT + NPTS;
    unsigned short* spermT = (unsigned short*)(szT + NPTS);
    unsigned int*   hist   = (unsigned int*)(spermT + NPTS);
    uint2* wk0 = (uint2*)(hist + NCELLS);           // key buffers (32 warps), 2 parities
    uint2* wk1 = wk0 + 32;
    unsigned int* s_bb = (unsigned int*)(wk1 + 32); // [0..5] bbox encoded
    int* s_p0 = (int*)(s_bb + 6);

    const float* cb = clouds + (size_t)b*4*NPTS;
    int t = threadIdx.x, lane = t & 31, w = t >> 5;

    if (t < 3)      s_bb[t] = 0xFFFFFFFFu;
    else if (t < 6) s_bb[t] = 0u;
    for (int c = t; c < NCELLS; c += NTHR) hist[c] = 0;
    __syncthreads();
    {
        float mnx=1e30f,mny=1e30f,mnz=1e30f,mxx=-1e30f,mxy=-1e30f,mxz=-1e30f;
        for (int j = 0; j < PPT; j++) {
            int i = t + j*NTHR;
            float x = cb[i], y = cb[NPTS+i], z = cb[2*NPTS+i];
            mnx = fminf(mnx,x); mny = fminf(mny,y); mnz = fminf(mnz,z);
            mxx = fmaxf(mxx,x); mxy = fmaxf(mxy,y); mxz = fmaxf(mxz,z);
        }
        #pragma unroll
        for (int off = 16; off > 0; off >>= 1) {
            mnx = fminf(mnx, __shfl_down_sync(0xffffffffu, mnx, off));
            mny = fminf(mny, __shfl_down_sync(0xffffffffu, mny, off));
            mnz = fminf(mnz, __shfl_down_sync(0xffffffffu, mnz, off));
            mxx = fmaxf(mxx, __shfl_down_sync(0xffffffffu, mxx, off));
            mxy = fmaxf(mxy, __shfl_down_sync(0xffffffffu, mxy, off));
            mxz = fmaxf(mxz, __shfl_down_sync(0xffffffffu, mxz, off));
        }
        if (lane == 0) {
            atomicMin(&s_bb[0], fenc_s(mnx));
            atomicMin(&s_bb[1], fenc_s(mny));
            atomicMin(&s_bb[2], fenc_s(mnz));
            atomicMax(&s_bb[3], fenc_s(mxx));
            atomicMax(&s_bb[4], fenc_s(mxy));
            atomicMax(&s_bb[5], fenc_s(mxz));
        }
    }
    __syncthreads();
    float gminx = fdec_s(s_bb[0]), gminy = fdec_s(s_bb[1]), gminz = fdec_s(s_bb[2]);
    float grx = 16.0f / fmaxf(fdec_s(s_bb[3]) - gminx, 1e-9f);
    float gry = 16.0f / fmaxf(fdec_s(s_bb[4]) - gminy, 1e-9f);
    float grz = 2.0f  / fmaxf(fdec_s(s_bb[5]) - gminz, 1e-9f);

    for (int j = 0; j < PPT; j++) {
        int i = t + j*NTHR;
        int cx = min(15, (int)((cb[i]        - gminx) * grx));
        int cy = min(15, (int)((cb[NPTS+i]   - gminy) * gry));
        int cz = min(1,  (int)((cb[2*NPTS+i] - gminz) * grz));
        int cell = (((mort4(cy) << 1) | mort4(cx)) << 1) | cz;
        atomicAdd(&hist[cell], 1u);
    }
    __syncthreads();
    for (int off = 1; off < NCELLS; off <<= 1) {
        unsigned v = 0;
        if (t < NCELLS && t >= off) v = hist[t-off];
        __syncthreads();
        if (t < NCELLS) hist[t] += v;
        __syncthreads();
    }
    {
        unsigned v = (t == 0) ? 0u : ((t < NCELLS) ? hist[t-1] : 0u);
        __syncthreads();
        if (t < NCELLS) hist[t] = v;
        __syncthreads();
    }
    for (int j = 0; j < PPT; j++) {
        int i = t + j*NTHR;
        float x = cb[i], y = cb[NPTS+i], z = cb[2*NPTS+i];
        int cx = min(15, (int)((x - gminx) * grx));
        int cy = min(15, (int)((y - gminy) * gry));
        int cz = min(1,  (int)((z - gminz) * grz));
        int cell = (((mort4(cy) << 1) | mort4(cx)) << 1) | cz;
        int p = (int)atomicAdd(&hist[cell], 1u);
        int phys = (p & 15)*NTHR + (p >> 4);
        sxT[phys] = x; syT[phys] = y; szT[phys] = z;
        spermT[phys] = (unsigned short)i;
        if (i == 0) *s_p0 = p;
    }
    __syncthreads();

    float dmin[PPT];
    float bxmin=1e30f, bymin=1e30f, bzmin=1e30f, bxmax=-1e30f, bymax=-1e30f, bzmax=-1e30f;
    #pragma unroll
    for (int j = 0; j < PPT; j++) {
        dmin[j] = 1e10f;
        float x = sxT[j*NTHR + t], y = syT[j*NTHR + t], z = szT[j*NTHR + t];
        bxmin = fminf(bxmin,x); bymin = fminf(bymin,y); bzmin = fminf(bzmin,z);
        bxmax = fmaxf(bxmax,x); bymax = fmaxf(bymax,y); bzmax = fmaxf(bzmax,z);
    }
    float bestv = 1e10f; int bestorig = 0x3fff; int bestsorted = t*PPT;
    unsigned wkh = 0u, wkl = 0u;
    unsigned champ_mask = 0xffffffffu;   // force reduce on first update
    int last = *s_p0;

    for (int it = 0; it < NKP; ++it) {
        if (t == 0) g_kp_sorted[b*NKP + it] = last;
        if (it == NKP-1) break;

        int lphys = (last & 15)*NTHR + (last >> 4);
        float lx = sxT[lphys], ly = syT[lphys], lz = szT[lphys];

        float dx = fmaxf(fmaxf(bxmin - lx, lx - bxmax), 0.f);
        float dy = fmaxf(fmaxf(bymin - ly, ly - bymax), 0.f);
        float dz = fmaxf(fmaxf(bzmin - lz, lz - bzmax), 0.f);
        float d2b = fmaf(dx, dx, fmaf(dy, dy, dz*dz));
        bool need = (d2b * 0.99999f) < bestv;

        if (need) {
            float bv = -1.f; int bo = 0x3fff, bs = t*PPT;
            #pragma unroll
            for (int j = 0; j < PPT; j++) {
                int phys = j*NTHR + t;
                float d  = dist2_ref(sxT[phys]-lx, syT[phys]-ly, szT[phys]-lz);
                float nd = fminf(dmin[j], d);
                dmin[j] = nd;
                int o = (int)spermT[phys];
                if (nd > bv || (nd == bv && o < bo)) { bv = nd; bo = o; bs = t*PPT + j; }
            }
            bestv = bv; bestorig = bo; bestsorted = bs;
        }
        unsigned m = __ballot_sync(0xffffffffu, need);
        if (m & champ_mask) {
            // warp key can only change if the champion thread updated
            unsigned fv = fenc(bestv);
            wkh = __reduce_max_sync(0xffffffffu, fv);
            unsigned lo = (fv == wkh) ? (((unsigned)(0x3fff - bestorig) << 14) | (unsigned)bestsorted) : 0u;
            wkl = __reduce_max_sync(0xffffffffu, lo);
            champ_mask = __ballot_sync(0xffffffffu, fv == wkh && lo == wkl);
        }
        uint2* wkb = (it & 1) ? wk1 : wk0;
        if (lane == 0) wkb[w] = make_uint2(wkh, wkl);
        __syncthreads();
        uint2 k = wkb[lane];
        unsigned mh = __reduce_max_sync(0xffffffffu, k.x);
        unsigned ml = __reduce_max_sync(0xffffffffu, (k.x == mh) ? k.y : 0u);
        last = (int)(ml & 0x3fffu);
        // single barrier per iter: double-buffered key table makes it race-free
    }
    __syncthreads();

    for (int k = t; k < NKP; k += NTHR) {
        int p = g_kp_sorted[b*NKP + k];
        int phys = (p & 15)*NTHR + (p >> 4);
        g_kp_xyz[(b*NKP+k)*3+0] = sxT[phys];
        g_kp_xyz[(b*NKP+k)*3+1] = syT[phys];
        g_kp_xyz[(b*NKP+k)*3+2] = szT[phys];
    }
    for (int p = t; p < NPTS; p += NTHR) {
        int phys = (p & 15)*NTHR + (p >> 4);
        g_sorted4[b*NPTS + p] = make_float4(sxT[phys], syT[phys], szT[phys],
                                            __int_as_float((int)spermT[phys]));
    }
    for (int c = t; c < NCELLS; c += NTHR) g_cell_end[b*NCELLS + c] = (int)hist[c];
    if (t == 0) {
        g_grid[b*8+0] = gminx; g_grid[b*8+1] = gminy; g_grid[b*8+2] = gminz;
        g_grid[b*8+3] = grx;   g_grid[b*8+4] = gry;   g_grid[b*8+5] = grz;
    }
}

// ===== K2: fused ball-query + rank (one warp per keypoint, candidates in smem) =====
__global__ __launch_bounds__(256) void ballq_select_kernel() {
    __shared__ float sd[8*CCAP];
    __shared__ int   si[8*CCAP];
    int w = threadIdx.x >> 5, lane = threadIdx.x & 31;
    int kp = blockIdx.x * 8 + w;
    int b = kp >> 12;
    float* swd = sd + w*CCAP; int* swi = si + w*CCAP;

    float kx = g_kp_xyz[kp*3+0], ky = g_kp_xyz[kp*3+1], kz = g_kp_xyz[kp*3+2];
    float gminx = g_grid[b*8+0], gminy = g_grid[b*8+1], gminz = g_grid[b*8+2];
    float grx = g_grid[b*8+3], gry = g_grid[b*8+4], grz = g_grid[b*8+5];
    const float4* sp4 = g_sorted4 + b*NPTS;
    const int* cend = g_cell_end + b*NCELLS;

    const float R = 1.6005f;   // pads float-rounding at the exact-radius boundary
    int cx0 = max(0, min(15, (int)floorf((kx - R - gminx) * grx)));
    int cx1 = max(0, min(15, (int)floorf((kx + R - gminx) * grx)));
    int cy0 = max(0, min(15, (int)floorf((ky - R - gminy) * gry)));
    int cy1 = max(0, min(15, (int)floorf((ky + R - gminy) * gry)));
    int cz0 = max(0, min(1,  (int)floorf((kz - R - gminz) * grz)));
    int cz1 = max(0, min(1,  (int)floorf((kz + R - gminz) * grz)));

    int cnt = 0;
    unsigned lmask = (1u << lane) - 1u;
    for (int cy = cy0; cy <= cy1; cy++) {
        for (int cx = cx0; cx <= cx1; cx++) {
            int base = ((mort4(cy) << 1) | mort4(cx)) << 1;
            int c0 = base | cz0, c1 = base | cz1;   // contiguous in sorted order
            int pstart = (c0 == 0) ? 0 : cend[c0-1];
            int pend = cend[c1];
            for (int p0 = pstart; p0 < pend; p0 += 32) {   // uniform trip count
                int p = p0 + lane;
                bool in = p < pend;
                float4 P = in ? sp4[p] : make_float4(1e30f, 1e30f, 1e30f, 0.f);
                float d2 = dist2_ref(kx - P.x, ky - P.y, kz - P.z);
                bool hit = in && (d2 < R2B_CONST);
                unsigned m = __ballot_sync(0xffffffffu, hit);
                if (hit) {
                    int pos = cnt + __popc(m & lmask);
                    if (pos < CCAP) {
                        swd[pos] = d2;
                        swi[pos] = __float_as_int(P.w);
                    }
                }
                cnt += __popc(m);   // cnt uniform across lanes
            }
        }
    }
    __syncwarp();

    int n = (cnt < CCAP) ? cnt : CCAP;
    int na = 0;
    for (int c = lane; c < n; c += 32) {
        float dc = swd[c];
        int oc = swi[c];
        int rank = 0;
        for (int c2 = 0; c2 < n; c2++) {
            float dv = swd[c2];
            rank += (dv < dc) || (dv == dc && swi[c2] < oc);  // ties -> lower orig idx
        }
        if (rank < 32) g_nbr[kp*32 + rank] = oc;
        if (rank < 16 && dc < R2A_CONST) na++;
    }
    #pragma unroll
    for (int off = 16; off > 0; off >>= 1) na += __shfl_down_sync(0xffffffffu, na, off);
    if (lane == 0) {
        g_cnt_a[kp] = na;
        g_cnt_b[kp] = (n < 32) ? n : 32;
    }
}

// ============ K4: PointNet MLP + max pool — register-tiled, relu-clamped ============
__global__ __launch_bounds__(256) void mlp_kernel(const float* __restrict__ clouds,
                                                  const float* __restrict__ w1a,
                                                  const float* __restrict__ w2a,
                                                  const float* __restrict__ w1b,
                                                  const float* __restrict__ w2b) {
    int kp = blockIdx.x;
    int b  = kp >> 12;
    __shared__ float sg[32][5];
    __shared__ float h1bt[128*32];
    __shared__ float h1at[128*16];
    __shared__ float partb[4][256];
    __shared__ float parta[2][256];
    __shared__ int   s_ca, s_cb;
    int t = threadIdx.x;
    if (t == 0) { s_ca = g_cnt_a[kp]; s_cb = g_cnt_b[kp]; }
    __syncthreads();
    int ca = s_ca, cb2 = s_cb;

    if (t < 32 && t < cb2) {
        int pi = g_nbr[kp*32 + t];
        const float* cbase = clouds + (size_t)b*4*NPTS;
        sg[t][0] = cbase[pi]        - g_kp_xyz[kp*3+0];
        sg[t][1] = cbase[NPTS+pi]   - g_kp_xyz[kp*3+1];
        sg[t][2] = cbase[2*NPTS+pi] - g_kp_xyz[kp*3+2];
        sg[t][3] = cbase[3*NPTS+pi];
    }
    __syncthreads();

    for (int e = t; e < 128*32; e += 256) {
        int j = e & 31, i = e >> 5;
        float v = 0.f;
        if (j < cb2) {
            float a = __fmul_rn(sg[j][0], w1b[i]);
            a = fmaf(sg[j][1], w1b[128+i], a);
            a = fmaf(sg[j][2], w1b[256+i], a);
            a = fmaf(sg[j][3], w1b[384+i], a);
            v = fmaxf(a, 0.f);
        }
        h1bt[i*32 + j] = v;
    }
    for (int e = t; e < 128*16; e += 256) {
        int j = e & 15, i = e >> 4;
        float v = 0.f;
        if (j < ca) {
            float a = __fmul_rn(sg[j][0], w1a[i]);
            a = fmaf(sg[j][1], w1a[128+i], a);
            a = fmaf(sg[j][2], w1a[256+i], a);
            a = fmaf(sg[j][3], w1a[384+i], a);
            v = fmaxf(a, 0.f);
        }
        h1at[i*16 + j] = v;
    }
    __syncthreads();

    // ---- scale b: thread = (jg = t>>6 in 0..3, cq = t&63 -> channels cq*4..+3) ----
    {
        int jg = t >> 6, cq = t & 63;
        unsigned long long acc[16];
        #pragma unroll
        for (int q = 0; q < 16; q++) acc[q] = 0ull;
        const float4* w2b4 = reinterpret_cast<const float4*>(w2b);
        for (int i = 0; i < 128; i++) {
            const ulonglong2* hp = reinterpret_cast<const ulonglong2*>(h1bt + i*32 + jg*8);
            ulonglong2 ha = hp[0], hb = hp[1];          // 8 j values = 4 pairs
            float4 wq = __ldg(&w2b4[i*64 + cq]);
            unsigned long long w0 = dup2(wq.x), w1 = dup2(wq.y),
                               w2d = dup2(wq.z), w3 = dup2(wq.w);
            ffma2(acc[0],  ha.x, w0); ffma2(acc[1],  ha.y, w0);
            ffma2(acc[2],  hb.x, w0); ffma2(acc[3],  hb.y, w0);
            ffma2(acc[4],  ha.x, w1); ffma2(acc[5],  ha.y, w1);
            ffma2(acc[6],  hb.x, w1); ffma2(acc[7],  hb.y, w1);
            ffma2(acc[8],  ha.x, w2d); ffma2(acc[9],  ha.y, w2d);
            ffma2(acc[10], hb.x, w2d); ffma2(acc[11], hb.y, w2d);
            ffma2(acc[12], ha.x, w3); ffma2(acc[13], ha.y, w3);
            ffma2(acc[14], hb.x, w3); ffma2(acc[15], hb.y, w3);
        }
        #pragma unroll
        for (int c = 0; c < 4; c++) {
            float v = fmaxf(fmaxf(pairmax(acc[c*4+0]), pairmax(acc[c*4+1])),
                            fmaxf(pairmax(acc[c*4+2]), pairmax(acc[c*4+3])));
            partb[jg][cq*4 + c] = v;
        }
    }

    // ---- scale a: thread = (jg2 = t>>7 in 0..1, cd = t&127 -> channels cd*2..+1) ----
    {
        int jg2 = t >> 7, cd = t & 127;
        unsigned long long acc[8];
        #pragma unroll
        for (int q = 0; q < 8; q++) acc[q] = 0ull;
        const float2* w2a2 = reinterpret_cast<const float2*>(w2a);
        for (int i = 0; i < 128; i++) {
            const ulonglong2* hp = reinterpret_cast<const ulonglong2*>(h1at + i*16 + jg2*8);
            ulonglong2 ha = hp[0], hb = hp[1];
            float2 wq = __ldg(&w2a2[i*128 + cd]);
            unsigned long long w0 = dup2(wq.x), w1 = dup2(wq.y);
            ffma2(acc[0], ha.x, w0); ffma2(acc[1], ha.y, w0);
            ffma2(acc[2], hb.x, w0); ffma2(acc[3], hb.y, w0);
            ffma2(acc[4], ha.x, w1); ffma2(acc[5], ha.y, w1);
            ffma2(acc[6], hb.x, w1); ffma2(acc[7], hb.y, w1);
        }
        #pragma unroll
        for (int c = 0; c < 2; c++) {
            float v = fmaxf(fmaxf(pairmax(acc[c*4+0]), pairmax(acc[c*4+1])),
                            fmaxf(pairmax(acc[c*4+2]), pairmax(acc[c*4+3])));
            parta[jg2][cd*2 + c] = v;
        }
    }
    __syncthreads();

    if (t < 64) {   // b channels: 4 per thread; relu clamp matches reference
        #pragma unroll
        for (int c = 0; c < 4; c++) {
            int ch = t*4 + c;
            float v = fmaxf(fmaxf(partb[0][ch], partb[1][ch]),
                            fmaxf(partb[2][ch], partb[3][ch]));
            g_pooled[kp*512 + 256 + ch] = fmaxf(v, 0.f);
        }
    } else if (t >= 128) {   // a channels: 2 per thread
        int tt = t - 128;
        #pragma unroll
        for (int c = 0; c < 2; c++) {
            int ch = tt*2 + c;
            float v = fmaxf(parta[0][ch], parta[1][ch]);
            g_pooled[kp*512 + ch] = fmaxf(v, 0.f);
        }
    }
}

// ============ K5: fusion + output (16 kp per block) ============
__global__ __launch_bounds__(128) void fuse_kernel(const float* __restrict__ wf,
                                                   float* __restrict__ out) {
    int kp0 = blockIdx.x * 16;
    __shared__ float sp[512*16];
    int t = threadIdx.x;
    for (int e = t; e < 512*16; e += 128) {
        int c = e & 511, q = e >> 9;
        sp[c*16 + q] = g_pooled[(size_t)(kp0 + q)*512 + c];
    }
    __syncthreads();
    unsigned long long acc[8];
    #pragma unroll
    for (int q = 0; q < 8; q++) acc[q] = 0ull;
    for (int c = 0; c < 512; c++) {
        unsigned long long wd = dup2(__ldg(&wf[c*128 + t]));
        const ulonglong2* pr = reinterpret_cast<const ulonglong2*>(sp + c*16);
        #pragma unroll
        for (int q4 = 0; q4 < 4; q4++) {
            ulonglong2 p2 = pr[q4];
            ffma2(acc[q4*2+0], p2.x, wd);
            ffma2(acc[q4*2+1], p2.y, wd);
        }
    }
    #pragma unroll
    for (int q = 0; q < 8; q++) {
        unsigned lo, hi;
        asm("mov.b64 {%0, %1}, %2;" : "=r"(lo), "=r"(hi) : "l"(acc[q]));
        out[(size_t)(kp0+q*2+0)*131 + 3 + t] = fmaxf(__uint_as_float(lo), 0.f);
        out[(size_t)(kp0+q*2+1)*131 + 3 + t] = fmaxf(__uint_as_float(hi), 0.f);
    }
    if (t < 48) {
        int q = t / 3, comp = t % 3;
        out[(size_t)(kp0+q)*131 + comp] = g_kp_xyz[(kp0+q)*3 + comp];
    }
}

extern "C" void kernel_launch(void* const* d_in, const int* in_sizes, int n_in,
                              void* d_out, int out_size) {
    const float* clouds = (const float*)d_in[0];
    const float* w1a    = (const float*)d_in[1];
    const float* w2a    = (const float*)d_in[2];
    const float* w1b    = (const float*)d_in[3];
    const float* w2b    = (const float*)d_in[4];
    const float* wf     = (const float*)d_in[5];
    float* out = (float*)d_out;

    // coords + perm + hist + 2x32 uint2 keys + bbox(6) + p0
    int fps_smem = 3*NPTS*4 + NPTS*2 + NCELLS*4 + 2*32*8 + 6*4 + 16;
    cudaFuncSetAttribute(fps_kernel, cudaFuncAttributeMaxDynamicSharedMemorySize, fps_smem);
    fps_kernel<<<BATCH, NTHR, fps_smem>>>(clouds);

    ballq_select_kernel<<<TOTKP/8, 256>>>();
    mlp_kernel<<<TOTKP, 256>>>(clouds, w1a, w2a, w1b, w2b);
    fuse_kernel<<<TOTKP/16, 128>>>(wf, out);
}